// round 2
// baseline (speedup 1.0000x reference)
#include <cuda_runtime.h>
#include <cuda_bf16.h>
#include <cub/cub.cuh>
#include <math.h>

// ---------------- constants ----------------
#define Hh 64
#define Ww 64
#define Cc 512
#define Mm 512
#define Nn 4
#define Aa 9
#define NPIX (Hh*Ww)              // 4096
#define NANCH (NPIX*Aa)           // 36864
#define PRE_N 3000
#define POST_N 300

#define LOC_OFF   0u
#define SCORE_OFF 589824u
#define ROIS_OFF  884736u
#define RI_OFF    889536u
#define ANCH_OFF  890736u

// ---------------- static device scratch (no allocs allowed) ----------------
__device__ float g_feat[(size_t)Nn*NPIX*Cc];          // NHWC feat, 33.5MB
__device__ float g_wT[(size_t)Cc*9*Mm];               // transposed conv weights [c][k][m]
__device__ float g_keys_in[Nn*NANCH];
__device__ float g_keys_out[Nn*NANCH];
__device__ int   g_vals_in[Nn*NANCH];
__device__ int   g_vals_out[Nn*NANCH];
__device__ int   g_offs[5];
__device__ float g_boxes[(size_t)Nn*NANCH*4];
__device__ float g_top[Nn*PRE_N*4];
__device__ float g_area[Nn*PRE_N];
__device__ unsigned long long g_cub_temp[(32u<<20)/8]; // 32MB

struct AB9 { float v[36]; };

// ---------------- weight transpose: OIHW -> [c][k][m] ----------------
__global__ void transpose_w_kernel(const float* __restrict__ w) {
    int idx = blockIdx.x * 256 + threadIdx.x;
    if (idx >= Mm*Cc*9) return;
    int m = idx / (Cc*9);
    int c = (idx / 9) % Cc;
    int k = idx % 9;
    g_wT[((size_t)c*9 + k)*Mm + m] = w[idx];
}

// ---------------- 3x3 conv + bias + relu, NCHW in -> NHWC feat ----------------
// grid: (64 spatial tiles of 8x8, 8 m-tiles of 64, n=4), 128 threads
// thread: mt = tid&15 (4 consecutive m), pt = tid>>4 (one 8-px row)
#define CB 8
__global__ __launch_bounds__(128) void conv3x3_kernel(const float* __restrict__ x,
                                                      const float* __restrict__ bias) {
    int tileid = blockIdx.x;
    int ty0 = (tileid >> 3) * 8;
    int tx0 = (tileid & 7) * 8;
    int m0 = blockIdx.y * 64;
    int n  = blockIdx.z;
    int tid = threadIdx.x;
    int mt = tid & 15, pt = tid >> 4;

    __shared__ __align__(16) float xs[CB][10][12];
    __shared__ __align__(16) float ws[CB][9][64];

    float acc[4][8];
#pragma unroll
    for (int i = 0; i < 4; i++)
#pragma unroll
        for (int j = 0; j < 8; j++) acc[i][j] = 0.f;

    const float* xn = x + (size_t)n * Cc * NPIX;

    for (int c0 = 0; c0 < Cc; c0 += CB) {
        __syncthreads();
        // load input tile with halo (zero pad)
        for (int i = tid; i < CB * 100; i += 128) {
            int c = i / 100, r = (i / 10) % 10, col = i % 10;
            int gy = ty0 + r - 1, gx = tx0 + col - 1;
            float v = 0.f;
            if ((unsigned)gy < Hh && (unsigned)gx < Ww)
                v = xn[(size_t)(c0 + c) * NPIX + gy * Ww + gx];
            xs[c][r][col] = v;
        }
        // load weights (coalesced from transposed layout)
        for (int i = tid; i < CB * 9 * 64; i += 128) {
            int c = i / (9 * 64);
            int k = (i / 64) % 9;
            int m = i & 63;
            ws[c][k][m] = g_wT[((size_t)(c0 + c) * 9 + k) * Mm + m0 + m];
        }
        __syncthreads();
#pragma unroll 1
        for (int c = 0; c < CB; c++) {
#pragma unroll
            for (int k = 0; k < 9; k++) {
                int ky = k / 3, kx = k % 3;
                float4 w4 = *(const float4*)&ws[c][k][mt * 4];
#pragma unroll
                for (int j = 0; j < 8; j++) {
                    float xv = xs[c][pt + ky][j + kx];
                    acc[0][j] = fmaf(w4.x, xv, acc[0][j]);
                    acc[1][j] = fmaf(w4.y, xv, acc[1][j]);
                    acc[2][j] = fmaf(w4.z, xv, acc[2][j]);
                    acc[3][j] = fmaf(w4.w, xv, acc[3][j]);
                }
            }
        }
    }
    float b0 = bias[m0 + mt*4 + 0], b1 = bias[m0 + mt*4 + 1];
    float b2 = bias[m0 + mt*4 + 2], b3 = bias[m0 + mt*4 + 3];
#pragma unroll
    for (int j = 0; j < 8; j++) {
        float4 o;
        o.x = fmaxf(acc[0][j] + b0, 0.f);
        o.y = fmaxf(acc[1][j] + b1, 0.f);
        o.z = fmaxf(acc[2][j] + b2, 0.f);
        o.w = fmaxf(acc[3][j] + b3, 0.f);
        *(float4*)&g_feat[(((size_t)n * Hh + ty0 + pt) * Ww + tx0 + j) * Cc + m0 + mt * 4] = o;
    }
}

// ---------------- 1x1 head + softmax + decode + clip + mask ----------------
__device__ __forceinline__ float readdim(const void* p) {
    int v = *(const int*)p;
    if (v > 0 && v < 1048576) return (float)v;
    return *(const float*)p;
}

// grid (512, 4), 256 threads = 8 warps; warp handles one pixel
__global__ __launch_bounds__(256) void rpn_head_kernel(
    const float* __restrict__ w_score, const float* __restrict__ b_score,
    const float* __restrict__ w_loc,   const float* __restrict__ b_loc,
    AB9 ab, const void* ihp, const void* iwp, float* __restrict__ out) {
    __shared__ float sh[8][56];
    int wid = threadIdx.x >> 5, lane = threadIdx.x & 31;
    int p = blockIdx.x * 8 + wid;
    int n = blockIdx.y;

    const float* f = g_feat + ((size_t)n * NPIX + p) * Cc;
    float fv[16];
#pragma unroll
    for (int i = 0; i < 16; i++) fv[i] = f[lane + 32 * i];

#pragma unroll 1
    for (int o = 0; o < 18; o++) {
        const float* w = w_score + o * Cc;
        float a = 0.f;
#pragma unroll
        for (int i = 0; i < 16; i++) a = fmaf(fv[i], w[lane + 32 * i], a);
#pragma unroll
        for (int s = 16; s; s >>= 1) a += __shfl_xor_sync(0xffffffffu, a, s);
        if (lane == 0) sh[wid][o] = a + b_score[o];
    }
#pragma unroll 1
    for (int o = 0; o < 36; o++) {
        const float* w = w_loc + o * Cc;
        float a = 0.f;
#pragma unroll
        for (int i = 0; i < 16; i++) a = fmaf(fv[i], w[lane + 32 * i], a);
#pragma unroll
        for (int s = 16; s; s >>= 1) a += __shfl_xor_sync(0xffffffffu, a, s);
        if (lane == 0) sh[wid][18 + o] = a + b_loc[o];
    }
    __syncwarp();

    if (lane < 9) {
        int a = lane;
        float s0 = sh[wid][a * 2], s1 = sh[wid][a * 2 + 1];
        size_t pa = (size_t)n * NANCH + (size_t)p * 9 + a;
        out[SCORE_OFF + pa * 2 + 0] = s0;
        out[SCORE_OFF + pa * 2 + 1] = s1;
        float l0 = sh[wid][18 + a * 4 + 0];
        float l1 = sh[wid][18 + a * 4 + 1];
        float l2 = sh[wid][18 + a * 4 + 2];
        float l3 = sh[wid][18 + a * 4 + 3];
        out[LOC_OFF + pa * 4 + 0] = l0;
        out[LOC_OFF + pa * 4 + 1] = l1;
        out[LOC_OFF + pa * 4 + 2] = l2;
        out[LOC_OFF + pa * 4 + 3] = l3;

        int py = p >> 6, px = p & 63;
        float sx = px * 16.f, sy = py * 16.f;
        float a0 = sx + ab.v[a * 4 + 0];
        float a1 = sy + ab.v[a * 4 + 1];
        float a2 = sx + ab.v[a * 4 + 2];
        float a3 = sy + ab.v[a * 4 + 3];
        if (n == 0) {
            size_t q = ((size_t)p * 9 + a) * 4;
            out[ANCH_OFF + q + 0] = a0;
            out[ANCH_OFF + q + 1] = a1;
            out[ANCH_OFF + q + 2] = a2;
            out[ANCH_OFF + q + 3] = a3;
        }
        float aw = a2 - a0, ah = a3 - a1;
        float cx = a0 + 0.5f * aw, cy = a1 + 0.5f * ah;
        float ncx = l0 * aw + cx, ncy = l1 * ah + cy;
        float nw = expf(l2) * aw, nh = expf(l3) * ah;
        float r0 = ncx - 0.5f * nw, r1 = ncy - 0.5f * nh;
        float r2 = ncx + 0.5f * nw, r3 = ncy + 0.5f * nh;
        float Wd = readdim(iwp), Hd = readdim(ihp);
        r0 = fminf(fmaxf(r0, 0.f), Wd);
        r1 = fminf(fmaxf(r1, 0.f), Hd);
        r2 = fminf(fmaxf(r2, 0.f), Wd);
        r3 = fminf(fmaxf(r3, 0.f), Hd);
        bool valid = ((r2 - r0) >= 16.f) && ((r3 - r1) >= 16.f);
        float m = fmaxf(s0, s1);
        float e0 = expf(s0 - m), e1 = expf(s1 - m);
        float fg = __fdiv_rn(e1, e0 + e1);
        g_keys_in[pa] = valid ? fg : -1e9f;
        float4 b4; b4.x = r0; b4.y = r1; b4.z = r2; b4.w = r3;
        ((float4*)g_boxes)[pa] = b4;
    }
}

// ---------------- sort setup ----------------
__global__ void init_sort_kernel() {
    int idx = blockIdx.x * 256 + threadIdx.x;
    if (idx < Nn * NANCH) g_vals_in[idx] = idx % NANCH;
    if (idx < 5) g_offs[idx] = idx * NANCH;
}

// ---------------- gather top-3000 boxes ----------------
__global__ void gather_kernel() {
    int idx = blockIdx.x * 256 + threadIdx.x;
    if (idx >= Nn * PRE_N) return;
    int n = idx / PRE_N, i = idx % PRE_N;
    int v = g_vals_out[n * NANCH + i];
    float4 b = ((const float4*)g_boxes)[(size_t)n * NANCH + v];
    ((float4*)g_top)[idx] = b;
    g_area[idx] = (b.z - b.x) * (b.w - b.y);
}

// ---------------- greedy NMS, one block per image ----------------
__global__ __launch_bounds__(256) void nms_kernel(float* __restrict__ out) {
    int n = blockIdx.x;
    int tid = threadIdx.x;
    __shared__ unsigned char sup[PRE_N];
    __shared__ int sel[POST_N];
    for (int i = tid; i < PRE_N; i += 256) sup[i] = 0;
    __syncthreads();

    const float* B = g_top + n * PRE_N * 4;
    const float* A = g_area + n * PRE_N;
    int cnt = 0;
    for (int i = 0; i < PRE_N; i++) {
        if (sup[i]) continue;            // uniform across block
        if (tid == 0) sel[cnt] = i;
        cnt++;
        if (cnt == POST_N) break;        // later boxes cannot affect first 300 keeps
        float x1 = B[i * 4 + 0], y1 = B[i * 4 + 1];
        float x2 = B[i * 4 + 2], y2 = B[i * 4 + 3];
        float ai = A[i];
        for (int j = i + 1 + tid; j < PRE_N; j += 256) {
            if (!sup[j]) {
                float xx1 = fmaxf(x1, B[j * 4 + 0]);
                float yy1 = fmaxf(y1, B[j * 4 + 1]);
                float xx2 = fminf(x2, B[j * 4 + 2]);
                float yy2 = fminf(y2, B[j * 4 + 3]);
                float inter = fmaxf(xx2 - xx1, 0.f) * fmaxf(yy2 - yy1, 0.f);
                float iou = __fdiv_rn(inter, ai + A[j] - inter + 1e-9f);
                if (iou > 0.7f) sup[j] = 1;
            }
        }
        __syncthreads();
    }
    __syncthreads();
    for (int k = tid; k < POST_N; k += 256) {
        int s = (k < cnt) ? sel[k] : 0;   // pad with box 0 (always kept)
        float4 b = ((const float4*)g_top)[n * PRE_N + s];
        size_t q = ((size_t)n * POST_N + k) * 4;
        out[ROIS_OFF + q + 0] = b.x;
        out[ROIS_OFF + q + 1] = b.y;
        out[ROIS_OFF + q + 2] = b.z;
        out[ROIS_OFF + q + 3] = b.w;
        out[RI_OFF + (size_t)n * POST_N + k] = (float)n;
    }
}

// ---------------- host: anchor base exactly like numpy (f64 -> f32) ----------------
static AB9 make_ab() {
    double ratios[3] = {0.5, 1.0, 2.0};
    double scales[3] = {8.0, 16.0, 32.0};
    AB9 r;
    for (int i = 0; i < 3; i++)
        for (int j = 0; j < 3; j++) {
            double h = 16.0 * scales[j] * sqrt(ratios[i]);
            double w = 16.0 * scales[j] * sqrt(1.0 / ratios[i]);
            int a = i * 3 + j;
            r.v[a * 4 + 0] = (float)(8.0 - w / 2.0);
            r.v[a * 4 + 1] = (float)(8.0 - h / 2.0);
            r.v[a * 4 + 2] = (float)(8.0 + w / 2.0);
            r.v[a * 4 + 3] = (float)(8.0 + h / 2.0);
        }
    return r;
}

extern "C" void kernel_launch(void* const* d_in, const int* in_sizes, int n_in,
                              void* d_out, int out_size) {
    const float* x       = (const float*)d_in[0];
    const float* w_conv  = (const float*)d_in[1];
    const float* b_conv  = (const float*)d_in[2];
    const float* w_score = (const float*)d_in[3];
    const float* b_score = (const float*)d_in[4];
    const float* w_loc   = (const float*)d_in[5];
    const float* b_loc   = (const float*)d_in[6];
    const void*  ihp     = d_in[7];
    const void*  iwp     = d_in[8];
    float* out = (float*)d_out;

    AB9 ab = make_ab();

    // 1) transpose conv weights for coalesced smem staging
    transpose_w_kernel<<<(Mm * Cc * 9 + 255) / 256, 256>>>(w_conv);

    // 2) 3x3 conv + relu -> NHWC feat
    conv3x3_kernel<<<dim3(64, 8, 4), 128>>>(x, b_conv);

    // 3) 1x1 heads + softmax + decode + clip + mask (+ write locs/scores/anchors)
    rpn_head_kernel<<<dim3(NPIX / 8, Nn), 256>>>(w_score, b_score, w_loc, b_loc,
                                                 ab, ihp, iwp, out);

    // 4) sort setup
    init_sort_kernel<<<(Nn * NANCH + 255) / 256, 256>>>();

    // 5) stable descending segmented sort (matches jax.lax.top_k tie semantics)
    void *keys_in, *keys_out, *vals_in, *vals_out, *offs, *tmp;
    cudaGetSymbolAddress(&keys_in, g_keys_in);
    cudaGetSymbolAddress(&keys_out, g_keys_out);
    cudaGetSymbolAddress(&vals_in, g_vals_in);
    cudaGetSymbolAddress(&vals_out, g_vals_out);
    cudaGetSymbolAddress(&offs, g_offs);
    cudaGetSymbolAddress(&tmp, g_cub_temp);
    size_t temp_bytes = sizeof(g_cub_temp);
    cub::DeviceSegmentedRadixSort::SortPairsDescending(
        tmp, temp_bytes,
        (const float*)keys_in, (float*)keys_out,
        (const int*)vals_in, (int*)vals_out,
        Nn * NANCH, Nn, (const int*)offs, (const int*)offs + 1,
        0, 32, (cudaStream_t)0);

    // 6) gather top-3000 boxes + areas
    gather_kernel<<<(Nn * PRE_N + 255) / 256, 256>>>();

    // 7) greedy NMS -> rois + roi_indices
    nms_kernel<<<Nn, 256>>>(out);
}